// round 7
// baseline (speedup 1.0000x reference)
#include <cuda_runtime.h>
#include <cuda_fp16.h>
#include <mma.h>

using namespace nvcuda;

#define NN 50000
#define NNP 50048              // 391 * 128, padded for unguarded wmma stores
#define NE 800000
#define FD 256
#define NB 196                 // (NN + 255) / 256 scan blocks

// ---------------- device scratch (no allocations allowed) ----------------
__device__ float  g_dis[NN];        // degree, then deg^-1/2 in place
__device__ int    g_cnt[NN];        // edge count per row
__device__ int    g_off[NN];        // CSR row offsets
__device__ int    g_cur[NN];        // scatter cursors
__device__ int    g_col[NE];        // CSR col indices
__device__ float  g_w[NE];          // CSR normalized weights
__device__ float  g_y[(size_t)NNP * FD];   // y = x @ W^T (fp32, padded rows)
__device__ __half g_yh[(size_t)NNP * FD];  // y in fp16 for SpMM gathers
__device__ int    g_blk[NB];
__device__ int    g_blkoff[NB];
__device__ int    g_is64;

__device__ __forceinline__ int edge_at(const void* ei, long long idx) {
    if (g_is64) return (int)((const long long*)ei)[idx];
    return ((const int*)ei)[idx];
}

// ---------------- init + dtype detect (block 0) ----------------
__global__ void k_init(const int* __restrict__ ei32) {
    int i = blockIdx.x * blockDim.x + threadIdx.x;
    if (i < NN) { g_dis[i] = 0.0f; g_cnt[i] = 0; }
    if (blockIdx.x == 0) {
        int nz = 0;
        if (threadIdx.x < 128) nz = (ei32[2 * threadIdx.x + 1] != 0) ? 1 : 0;
        int any = __syncthreads_or(nz);
        if (threadIdx.x == 0) g_is64 = (any == 0) ? 1 : 0;
    }
}

// ---------------- degree accumulation ----------------
__global__ void k_deg(const void* __restrict__ ei, const float* __restrict__ C) {
    int e = blockIdx.x * blockDim.x + threadIdx.x;
    if (e < NE) {
        int r = edge_at(ei, e);
        atomicAdd(&g_dis[r], C[e]);
        atomicAdd(&g_cnt[r], 1);
    }
}

// ---------------- hierarchical scan ----------------
__global__ __launch_bounds__(256) void k_scan1() {
    __shared__ int s[256];
    int t = threadIdx.x;
    int i = blockIdx.x * 256 + t;
    int v = 0;
    if (i < NN) {
        float d = g_dis[i];
        g_dis[i] = (d > 0.0f) ? rsqrtf(d) : 0.0f;
        v = g_cnt[i];
    }
    s[t] = v;
    __syncthreads();
#pragma unroll
    for (int off = 128; off > 0; off >>= 1) {
        if (t < off) s[t] += s[t + off];
        __syncthreads();
    }
    if (t == 0) g_blk[blockIdx.x] = s[0];
}

__global__ __launch_bounds__(256) void k_scan2() {
    __shared__ int s[256];
    int t = threadIdx.x;
    int v = (t < NB) ? g_blk[t] : 0;
    s[t] = v;
    __syncthreads();
#pragma unroll
    for (int off = 1; off < 256; off <<= 1) {
        int u = (t >= off) ? s[t - off] : 0;
        __syncthreads();
        s[t] += u;
        __syncthreads();
    }
    if (t < NB) g_blkoff[t] = s[t] - v;
}

__global__ __launch_bounds__(256) void k_scan3() {
    __shared__ int s[256];
    int t = threadIdx.x;
    int i = blockIdx.x * 256 + t;
    int v = (i < NN) ? g_cnt[i] : 0;
    s[t] = v;
    __syncthreads();
#pragma unroll
    for (int off = 1; off < 256; off <<= 1) {
        int u = (t >= off) ? s[t - off] : 0;
        __syncthreads();
        s[t] += u;
        __syncthreads();
    }
    if (i < NN) {
        int excl = g_blkoff[blockIdx.x] + s[t] - v;
        g_off[i] = excl;
        g_cur[i] = excl;
    }
}

// ---------------- scatter edges into CSR ----------------
__global__ void k_scatter(const void* __restrict__ ei, const float* __restrict__ C) {
    int e = blockIdx.x * blockDim.x + threadIdx.x;
    if (e < NE) {
        int r  = edge_at(ei, e);
        int cl = edge_at(ei, (long long)NE + e);
        float w = g_dis[r] * C[e] * g_dis[cl];
        int p = atomicAdd(&g_cur[r], 1);
        g_col[p] = cl;
        g_w[p]   = w;
    }
}

// ---------------- tf32 tensor-core GEMM (one 128-col feature half) ------
#define GM_BM 128
#define GM_BN 128
#define GM_BK 16
#define BKP   20   // padded ld (floats)

__device__ __forceinline__ float4 cvt4(float4 v) {
    v.x = wmma::__float_to_tf32(v.x);
    v.y = wmma::__float_to_tf32(v.y);
    v.z = wmma::__float_to_tf32(v.z);
    v.w = wmma::__float_to_tf32(v.w);
    return v;
}

__global__ __launch_bounds__(256) void k_gemm_tc(const float* __restrict__ A,
                                                 const float* __restrict__ B,
                                                 int n0) {
    __shared__ __align__(16) float As[2][GM_BM][BKP];
    __shared__ __align__(16) float Bs[2][GM_BN][BKP];

    const int tid = threadIdx.x;
    const int w  = tid >> 5;
    const int wm = w >> 2;     // 0..1 -> 64-row slab
    const int wn = w & 3;      // 0..3 -> 32-col slab
    const int bm = blockIdx.x;

    wmma::fragment<wmma::accumulator, 16, 16, 8, float> acc[4][2];
#pragma unroll
    for (int i = 0; i < 4; i++)
#pragma unroll
        for (int j = 0; j < 2; j++) wmma::fill_fragment(acc[i][j], 0.0f);

    int aR[2], aC[2];
#pragma unroll
    for (int i = 0; i < 2; i++) {
        int f = tid + 256 * i;
        aR[i] = f >> 2;
        aC[i] = (f & 3) * 4;
    }
    int gAr[2]; bool av[2]; int gBr[2];
#pragma unroll
    for (int i = 0; i < 2; i++) {
        gAr[i] = bm * GM_BM + aR[i];
        av[i]  = (gAr[i] < NN);
        gBr[i] = n0 + aR[i];
    }

    const float4 z4 = make_float4(0.f, 0.f, 0.f, 0.f);
    float4 ra[2], rb[2];

#pragma unroll
    for (int i = 0; i < 2; i++) {
        ra[i] = av[i] ? *(const float4*)(A + (size_t)gAr[i] * FD + aC[i]) : z4;
        rb[i] = *(const float4*)(B + (size_t)gBr[i] * FD + aC[i]);
    }
#pragma unroll
    for (int i = 0; i < 2; i++) {
        *(float4*)&As[0][aR[i]][aC[i]] = cvt4(ra[i]);
        *(float4*)&Bs[0][aR[i]][aC[i]] = cvt4(rb[i]);
    }
    __syncthreads();

    const int NCH = FD / GM_BK; // 16
    for (int c = 0; c < NCH; c++) {
        const int p = c & 1, q = p ^ 1;
        if (c < NCH - 1) {
            const int k0 = (c + 1) * GM_BK;
#pragma unroll
            for (int i = 0; i < 2; i++) {
                ra[i] = av[i] ? *(const float4*)(A + (size_t)gAr[i] * FD + k0 + aC[i]) : z4;
                rb[i] = *(const float4*)(B + (size_t)gBr[i] * FD + k0 + aC[i]);
            }
        }

#pragma unroll
        for (int ks = 0; ks < 2; ks++) {
            const int k0 = ks * 8;
            wmma::fragment<wmma::matrix_a, 16, 16, 8, wmma::precision::tf32, wmma::row_major> af[4];
            wmma::fragment<wmma::matrix_b, 16, 16, 8, wmma::precision::tf32, wmma::col_major> bf[2];
#pragma unroll
            for (int i = 0; i < 4; i++)
                wmma::load_matrix_sync(af[i], &As[p][wm * 64 + i * 16][k0], BKP);
#pragma unroll
            for (int j = 0; j < 2; j++)
                wmma::load_matrix_sync(bf[j], &Bs[p][wn * 32 + j * 16][k0], BKP);
#pragma unroll
            for (int i = 0; i < 4; i++)
#pragma unroll
                for (int j = 0; j < 2; j++)
                    wmma::mma_sync(acc[i][j], af[i], bf[j], acc[i][j]);
        }

        if (c < NCH - 1) {
#pragma unroll
            for (int i = 0; i < 2; i++) {
                *(float4*)&As[q][aR[i]][aC[i]] = cvt4(ra[i]);
                *(float4*)&Bs[q][aR[i]][aC[i]] = cvt4(rb[i]);
            }
            __syncthreads();
        }
    }

#pragma unroll
    for (int i = 0; i < 4; i++) {
        int gr = bm * GM_BM + wm * 64 + i * 16;
#pragma unroll
        for (int j = 0; j < 2; j++) {
            int gc = n0 + wn * 32 + j * 16;
            wmma::store_matrix_sync(g_y + (size_t)gr * FD + gc, acc[i][j], FD,
                                    wmma::mem_row_major);
        }
    }
}

// ---------------- fp32 -> fp16 conversion for one feature half ----------
// idx4 covers NNP rows x 32 float4 (=128 cols) per half.
__global__ __launch_bounds__(256) void k_cvt(int n0) {
    long long idx4 = (long long)blockIdx.x * blockDim.x + threadIdx.x;
    const long long total = (long long)NNP * 32;
    if (idx4 >= total) return;
    int row = (int)(idx4 >> 5);
    int c4  = ((int)idx4 & 31) * 4;
    size_t base = (size_t)row * FD + n0 + c4;
    float4 v = *(const float4*)(g_y + base);
    __half2* dst = (__half2*)(g_yh + base);
    dst[0] = __floats2half2_rn(v.x, v.y);
    dst[1] = __floats2half2_rn(v.z, v.w);
}

// ---------------- SpMM (one 128-col feature half): warp per row ----------
// lane handles 4 cols (uint2 = 4 halves). Accumulate fp32.
__global__ __launch_bounds__(256) void k_spmm(const float* __restrict__ bias,
                                              float* __restrict__ out,
                                              int n0) {
    int gwarp = (blockIdx.x * blockDim.x + threadIdx.x) >> 5;
    int lane  = threadIdx.x & 31;
    if (gwarp >= NN) return;

    const int beg = g_off[gwarp];
    const int end = beg + g_cnt[gwarp];
    const int fc  = n0 + lane * 4;

    float4 acc = *(const float4*)(bias + fc);

    int p = beg;
    for (; p + 3 < end; p += 4) {
        int   c0 = g_col[p],     c1 = g_col[p + 1];
        int   c2 = g_col[p + 2], c3 = g_col[p + 3];
        float w0 = g_w[p],       w1 = g_w[p + 1];
        float w2 = g_w[p + 2],   w3 = g_w[p + 3];
        const __half2* y0 = (const __half2*)(g_yh + (size_t)c0 * FD + fc);
        const __half2* y1 = (const __half2*)(g_yh + (size_t)c1 * FD + fc);
        const __half2* y2 = (const __half2*)(g_yh + (size_t)c2 * FD + fc);
        const __half2* y3 = (const __half2*)(g_yh + (size_t)c3 * FD + fc);
        float2 u0 = __half22float2(y0[0]), u1 = __half22float2(y0[1]);
        float2 v0 = __half22float2(y1[0]), v1 = __half22float2(y1[1]);
        float2 s0 = __half22float2(y2[0]), s1 = __half22float2(y2[1]);
        float2 t0 = __half22float2(y3[0]), t1 = __half22float2(y3[1]);
        acc.x = fmaf(w0, u0.x, acc.x); acc.y = fmaf(w0, u0.y, acc.y);
        acc.z = fmaf(w0, u1.x, acc.z); acc.w = fmaf(w0, u1.y, acc.w);
        acc.x = fmaf(w1, v0.x, acc.x); acc.y = fmaf(w1, v0.y, acc.y);
        acc.z = fmaf(w1, v1.x, acc.z); acc.w = fmaf(w1, v1.y, acc.w);
        acc.x = fmaf(w2, s0.x, acc.x); acc.y = fmaf(w2, s0.y, acc.y);
        acc.z = fmaf(w2, s1.x, acc.z); acc.w = fmaf(w2, s1.y, acc.w);
        acc.x = fmaf(w3, t0.x, acc.x); acc.y = fmaf(w3, t0.y, acc.y);
        acc.z = fmaf(w3, t1.x, acc.z); acc.w = fmaf(w3, t1.y, acc.w);
    }
    for (; p < end; p++) {
        float wv = g_w[p];
        const __half2* yr = (const __half2*)(g_yh + (size_t)g_col[p] * FD + fc);
        float2 u0 = __half22float2(yr[0]), u1 = __half22float2(yr[1]);
        acc.x = fmaf(wv, u0.x, acc.x); acc.y = fmaf(wv, u0.y, acc.y);
        acc.z = fmaf(wv, u1.x, acc.z); acc.w = fmaf(wv, u1.y, acc.w);
    }

    *(float4*)(out + (size_t)gwarp * FD + fc) = acc;
}

// ---------------- launch: two-half GEMM->cvt->SpMM pipeline --------------
extern "C" void kernel_launch(void* const* d_in, const int* in_sizes, int n_in,
                              void* d_out, int out_size) {
    const float* x  = (const float*)d_in[0];
    const void*  ei = d_in[1];
    const float* C  = (const float*)d_in[2];
    const float* W  = (const float*)d_in[3];
    const float* b  = (const float*)d_in[4];
    float* out = (float*)d_out;

    cudaStream_t s2;
    cudaStreamCreateWithFlags(&s2, cudaStreamNonBlocking);
    cudaEvent_t eFork, e0, e1;
    cudaEventCreateWithFlags(&eFork, cudaEventDisableTiming);
    cudaEventCreateWithFlags(&e0, cudaEventDisableTiming);
    cudaEventCreateWithFlags(&e1, cudaEventDisableTiming);

    const int cvtBlocks = (int)(((long long)NNP * 32 + 255) / 256);

    cudaEventRecord(eFork, 0);
    cudaStreamWaitEvent(s2, eFork, 0);
    k_gemm_tc<<<NNP / GM_BM, 256, 0, s2>>>(x, W, 0);
    k_cvt<<<cvtBlocks, 256, 0, s2>>>(0);
    cudaEventRecord(e0, s2);
    k_gemm_tc<<<NNP / GM_BM, 256, 0, s2>>>(x, W, 128);
    k_cvt<<<cvtBlocks, 256, 0, s2>>>(128);
    cudaEventRecord(e1, s2);

    // CSR build pipeline on the default stream (hidden under GEMM_h0)
    k_init<<<(NN + 255) / 256, 256>>>((const int*)ei);
    k_deg<<<(NE + 255) / 256, 256>>>(ei, C);
    k_scan1<<<NB, 256>>>();
    k_scan2<<<1, 256>>>();
    k_scan3<<<NB, 256>>>();
    k_scatter<<<(NE + 255) / 256, 256>>>(ei, C);

    // SpMM_h0 overlaps GEMM_h1; SpMM_h1 after cvt_h1
    cudaStreamWaitEvent(0, e0, 0);
    k_spmm<<<(NN * 32 + 255) / 256, 256>>>(b, out, 0);
    cudaStreamWaitEvent(0, e1, 0);
    k_spmm<<<(NN * 32 + 255) / 256, 256>>>(b, out, 128);
}

// round 8
// speedup vs baseline: 1.0278x; 1.0278x over previous
#include <cuda_runtime.h>
#include <cuda_fp16.h>
#include <mma.h>
#include <cstdint>

using namespace nvcuda;

#define NN 50000
#define NNP 50048              // 391 * 128, padded rows
#define NE 800000
#define FD 256
#define NB 196                 // (NN + 255) / 256 scan blocks

// ---------------- device scratch (no allocations allowed) ----------------
__device__ float  g_dis[NN];
__device__ int    g_cnt[NN];
__device__ int    g_off[NN];
__device__ int    g_cur[NN];
__device__ int    g_col[NE];
__device__ float  g_w[NE];
__device__ __half g_yh[(size_t)NNP * FD];  // y = x @ W^T in fp16
__device__ int    g_blk[NB];
__device__ int    g_blkoff[NB];
__device__ int    g_is64;

__device__ __forceinline__ int edge_at(const void* ei, long long idx) {
    if (g_is64) return (int)((const long long*)ei)[idx];
    return ((const int*)ei)[idx];
}

// ---------------- cp.async helpers ----------------
__device__ __forceinline__ uint32_t smem_u32(const void* p) {
    uint32_t a;
    asm("{ .reg .u64 t; cvta.to.shared.u64 t, %1; cvt.u32.u64 %0, t; }" : "=r"(a) : "l"(p));
    return a;
}
__device__ __forceinline__ void cp_async16(uint32_t dst, const void* src, int srcBytes) {
    asm volatile("cp.async.cg.shared.global [%0], [%1], 16, %2;"
                 :: "r"(dst), "l"(src), "r"(srcBytes) : "memory");
}
#define CP_COMMIT() asm volatile("cp.async.commit_group;" ::: "memory")
#define CP_WAIT1()  asm volatile("cp.async.wait_group 1;" ::: "memory")
#define CP_WAIT0()  asm volatile("cp.async.wait_group 0;" ::: "memory")

// ---------------- init + dtype detect ----------------
__global__ void k_init(const int* __restrict__ ei32) {
    int i = blockIdx.x * blockDim.x + threadIdx.x;
    if (i < NN) { g_dis[i] = 0.0f; g_cnt[i] = 0; }
    if (blockIdx.x == 0) {
        int nz = 0;
        if (threadIdx.x < 128) nz = (ei32[2 * threadIdx.x + 1] != 0) ? 1 : 0;
        int any = __syncthreads_or(nz);
        if (threadIdx.x == 0) g_is64 = (any == 0) ? 1 : 0;
    }
}

__global__ void k_deg(const void* __restrict__ ei, const float* __restrict__ C) {
    int e = blockIdx.x * blockDim.x + threadIdx.x;
    if (e < NE) {
        int r = edge_at(ei, e);
        atomicAdd(&g_dis[r], C[e]);
        atomicAdd(&g_cnt[r], 1);
    }
}

__global__ __launch_bounds__(256) void k_scan1() {
    __shared__ int s[256];
    int t = threadIdx.x;
    int i = blockIdx.x * 256 + t;
    int v = 0;
    if (i < NN) {
        float d = g_dis[i];
        g_dis[i] = (d > 0.0f) ? rsqrtf(d) : 0.0f;
        v = g_cnt[i];
    }
    s[t] = v;
    __syncthreads();
#pragma unroll
    for (int off = 128; off > 0; off >>= 1) {
        if (t < off) s[t] += s[t + off];
        __syncthreads();
    }
    if (t == 0) g_blk[blockIdx.x] = s[0];
}

__global__ __launch_bounds__(256) void k_scan2() {
    __shared__ int s[256];
    int t = threadIdx.x;
    int v = (t < NB) ? g_blk[t] : 0;
    s[t] = v;
    __syncthreads();
#pragma unroll
    for (int off = 1; off < 256; off <<= 1) {
        int u = (t >= off) ? s[t - off] : 0;
        __syncthreads();
        s[t] += u;
        __syncthreads();
    }
    if (t < NB) g_blkoff[t] = s[t] - v;
}

__global__ __launch_bounds__(256) void k_scan3() {
    __shared__ int s[256];
    int t = threadIdx.x;
    int i = blockIdx.x * 256 + t;
    int v = (i < NN) ? g_cnt[i] : 0;
    s[t] = v;
    __syncthreads();
#pragma unroll
    for (int off = 1; off < 256; off <<= 1) {
        int u = (t >= off) ? s[t - off] : 0;
        __syncthreads();
        s[t] += u;
        __syncthreads();
    }
    if (i < NN) {
        int excl = g_blkoff[blockIdx.x] + s[t] - v;
        g_off[i] = excl;
        g_cur[i] = excl;
    }
}

__global__ void k_scatter(const void* __restrict__ ei, const float* __restrict__ C) {
    int e = blockIdx.x * blockDim.x + threadIdx.x;
    if (e < NE) {
        int r  = edge_at(ei, e);
        int cl = edge_at(ei, (long long)NE + e);
        float w = g_dis[r] * C[e] * g_dis[cl];
        int p = atomicAdd(&g_cur[r], 1);
        g_col[p] = cl;
        g_w[p]   = w;
    }
}

// ---------------- tf32 tensor-core GEMM (one 128-col feature half) ------
// y_h16[:, n0:n0+128] = (half) x[M,256] @ W[n0:n0+128, :]^T
// Block 128x128, 8 warps (2x4), warp 64x32 (4x2 m16n16k8 tf32).
// cp.async double-buffered BK=16; fp16 epilogue via smem staging.
#define GM_BM 128
#define GM_BK 16
#define BKP   20   // padded ld (floats); row stride 80B (16B-aligned)

__global__ __launch_bounds__(256) void k_gemm_tc(const float* __restrict__ A,
                                                 const float* __restrict__ B,
                                                 int n0) {
    __shared__ __align__(16) float As[2][GM_BM][BKP];   // 20 KB
    __shared__ __align__(16) float Bs[2][GM_BM][BKP];   // 20 KB

    const int tid  = threadIdx.x;
    const int wid  = tid >> 5;
    const int lane = tid & 31;
    const int wm = wid >> 2;     // 0..1 -> 64-row slab
    const int wn = wid & 3;      // 0..3 -> 32-col slab
    const int bm = blockIdx.x;

    wmma::fragment<wmma::accumulator, 16, 16, 8, float> acc[4][2];
#pragma unroll
    for (int i = 0; i < 4; i++)
#pragma unroll
        for (int j = 0; j < 2; j++) wmma::fill_fragment(acc[i][j], 0.0f);

    // per chunk: 128x16 floats = 512 float4 per tile -> 2 per thread per tile
    int aR[2], aC[2];
#pragma unroll
    for (int i = 0; i < 2; i++) {
        int f = tid + 256 * i;
        aR[i] = f >> 2;          // 0..127
        aC[i] = (f & 3) * 4;     // 0,4,8,12
    }
    int gAr[2], szA[2], gBr[2];
#pragma unroll
    for (int i = 0; i < 2; i++) {
        gAr[i] = bm * GM_BM + aR[i];
        szA[i] = (gAr[i] < NN) ? 16 : 0;    // zero-fill OOB rows
        gBr[i] = n0 + aR[i];
    }

    uint32_t sa[2][2], sb[2][2];
#pragma unroll
    for (int b = 0; b < 2; b++)
#pragma unroll
        for (int i = 0; i < 2; i++) {
            sa[b][i] = smem_u32(&As[b][aR[i]][aC[i]]);
            sb[b][i] = smem_u32(&Bs[b][aR[i]][aC[i]]);
        }

    auto issue = [&](int k, int buf) {
        const int k0 = k * GM_BK;
#pragma unroll
        for (int i = 0; i < 2; i++) {
            cp_async16(sa[buf][i], A + (size_t)gAr[i] * FD + k0 + aC[i], szA[i]);
            cp_async16(sb[buf][i], B + (size_t)gBr[i] * FD + k0 + aC[i], 16);
        }
        CP_COMMIT();
    };

    issue(0, 0);
    issue(1, 1);
    CP_WAIT1();
    __syncthreads();

    const int NCH = FD / GM_BK; // 16
    for (int c = 0; c < NCH; c++) {
        const int p = c & 1;

#pragma unroll
        for (int ks = 0; ks < 2; ks++) {
            const int k0 = ks * 8;
            wmma::fragment<wmma::matrix_a, 16, 16, 8, wmma::precision::tf32, wmma::row_major> af[4];
            wmma::fragment<wmma::matrix_b, 16, 16, 8, wmma::precision::tf32, wmma::col_major> bf[2];
#pragma unroll
            for (int i = 0; i < 4; i++)
                wmma::load_matrix_sync(af[i], &As[p][wm * 64 + i * 16][k0], BKP);
#pragma unroll
            for (int j = 0; j < 2; j++)
                wmma::load_matrix_sync(bf[j], &Bs[p][wn * 32 + j * 16][k0], BKP);
#pragma unroll
            for (int i = 0; i < 4; i++)
#pragma unroll
                for (int j = 0; j < 2; j++)
                    wmma::mma_sync(acc[i][j], af[i], bf[j], acc[i][j]);
        }

        if (c < NCH - 2) {
            __syncthreads();            // all warps done with buf p
            issue(c + 2, p);
            CP_WAIT1();                 // chunk c+1 resident
            __syncthreads();
        } else if (c == NCH - 2) {
            CP_WAIT0();                 // last chunk resident
            __syncthreads();
        }
    }

    // ---------------- fp16 epilogue via smem staging ----------------
    __syncthreads();                    // retire As/Bs, reuse as staging
    float* stage = &As[0][0][0] + wid * 336;   // 16x20 tile + pad per warp
    const int srow = lane >> 1;
    const int scol = (lane & 1) * 8;
#pragma unroll
    for (int i = 0; i < 4; i++) {
#pragma unroll
        for (int j = 0; j < 2; j++) {
            wmma::store_matrix_sync(stage, acc[i][j], 20, wmma::mem_row_major);
            __syncwarp();
            const float* sp = stage + srow * 20 + scol;
            __half2 h0 = __floats2half2_rn(sp[0], sp[1]);
            __half2 h1 = __floats2half2_rn(sp[2], sp[3]);
            __half2 h2 = __floats2half2_rn(sp[4], sp[5]);
            __half2 h3 = __floats2half2_rn(sp[6], sp[7]);
            int gr = bm * GM_BM + wm * 64 + i * 16 + srow;
            int gc = n0 + wn * 32 + j * 16 + scol;
            __half2* dst = (__half2*)(g_yh + (size_t)gr * FD + gc);
            dst[0] = h0; dst[1] = h1; dst[2] = h2; dst[3] = h3;
            __syncwarp();
        }
    }
}

// ---------------- SpMM (one 128-col feature half): warp per row ----------
__global__ __launch_bounds__(256) void k_spmm(const float* __restrict__ bias,
                                              float* __restrict__ out,
                                              int n0) {
    int gwarp = (blockIdx.x * blockDim.x + threadIdx.x) >> 5;
    int lane  = threadIdx.x & 31;
    if (gwarp >= NN) return;

    const int beg = g_off[gwarp];
    const int end = beg + g_cnt[gwarp];
    const int fc  = n0 + lane * 4;

    float4 acc = *(const float4*)(bias + fc);

    int p = beg;
    for (; p + 3 < end; p += 4) {
        int   c0 = g_col[p],     c1 = g_col[p + 1];
        int   c2 = g_col[p + 2], c3 = g_col[p + 3];
        float w0 = g_w[p],       w1 = g_w[p + 1];
        float w2 = g_w[p + 2],   w3 = g_w[p + 3];
        const __half2* y0 = (const __half2*)(g_yh + (size_t)c0 * FD + fc);
        const __half2* y1 = (const __half2*)(g_yh + (size_t)c1 * FD + fc);
        const __half2* y2 = (const __half2*)(g_yh + (size_t)c2 * FD + fc);
        const __half2* y3 = (const __half2*)(g_yh + (size_t)c3 * FD + fc);
        float2 u0 = __half22float2(y0[0]), u1 = __half22float2(y0[1]);
        float2 v0 = __half22float2(y1[0]), v1 = __half22float2(y1[1]);
        float2 s0 = __half22float2(y2[0]), s1 = __half22float2(y2[1]);
        float2 t0 = __half22float2(y3[0]), t1 = __half22float2(y3[1]);
        acc.x = fmaf(w0, u0.x, acc.x); acc.y = fmaf(w0, u0.y, acc.y);
        acc.z = fmaf(w0, u1.x, acc.z); acc.w = fmaf(w0, u1.y, acc.w);
        acc.x = fmaf(w1, v0.x, acc.x); acc.y = fmaf(w1, v0.y, acc.y);
        acc.z = fmaf(w1, v1.x, acc.z); acc.w = fmaf(w1, v1.y, acc.w);
        acc.x = fmaf(w2, s0.x, acc.x); acc.y = fmaf(w2, s0.y, acc.y);
        acc.z = fmaf(w2, s1.x, acc.z); acc.w = fmaf(w2, s1.y, acc.w);
        acc.x = fmaf(w3, t0.x, acc.x); acc.y = fmaf(w3, t0.y, acc.y);
        acc.z = fmaf(w3, t1.x, acc.z); acc.w = fmaf(w3, t1.y, acc.w);
    }
    for (; p < end; p++) {
        float wv = g_w[p];
        const __half2* yr = (const __half2*)(g_yh + (size_t)g_col[p] * FD + fc);
        float2 u0 = __half22float2(yr[0]), u1 = __half22float2(yr[1]);
        acc.x = fmaf(wv, u0.x, acc.x); acc.y = fmaf(wv, u0.y, acc.y);
        acc.z = fmaf(wv, u1.x, acc.z); acc.w = fmaf(wv, u1.y, acc.w);
    }

    *(float4*)(out + (size_t)gwarp * FD + fc) = acc;
}

// ---------------- launch: two-half GEMM->SpMM pipeline -------------------
extern "C" void kernel_launch(void* const* d_in, const int* in_sizes, int n_in,
                              void* d_out, int out_size) {
    const float* x  = (const float*)d_in[0];
    const void*  ei = d_in[1];
    const float* C  = (const float*)d_in[2];
    const float* W  = (const float*)d_in[3];
    const float* b  = (const float*)d_in[4];
    float* out = (float*)d_out;

    cudaStream_t s2;
    cudaStreamCreateWithFlags(&s2, cudaStreamNonBlocking);
    cudaEvent_t eFork, e0, e1;
    cudaEventCreateWithFlags(&eFork, cudaEventDisableTiming);
    cudaEventCreateWithFlags(&e0, cudaEventDisableTiming);
    cudaEventCreateWithFlags(&e1, cudaEventDisableTiming);

    cudaEventRecord(eFork, 0);
    cudaStreamWaitEvent(s2, eFork, 0);
    k_gemm_tc<<<NNP / GM_BM, 256, 0, s2>>>(x, W, 0);
    cudaEventRecord(e0, s2);
    k_gemm_tc<<<NNP / GM_BM, 256, 0, s2>>>(x, W, 128);
    cudaEventRecord(e1, s2);

    // CSR build pipeline on the default stream (hidden under GEMM_h0)
    k_init<<<(NN + 255) / 256, 256>>>((const int*)ei);
    k_deg<<<(NE + 255) / 256, 256>>>(ei, C);
    k_scan1<<<NB, 256>>>();
    k_scan2<<<1, 256>>>();
    k_scan3<<<NB, 256>>>();
    k_scatter<<<(NE + 255) / 256, 256>>>(ei, C);

    // SpMM_h0 overlaps GEMM_h1; SpMM_h1 after GEMM_h1
    cudaStreamWaitEvent(0, e0, 0);
    k_spmm<<<(NN * 32 + 255) / 256, 256>>>(b, out, 0);
    cudaStreamWaitEvent(0, e1, 0);
    k_spmm<<<(NN * 32 + 255) / 256, 256>>>(b, out, 128);
}

// round 10
// speedup vs baseline: 1.4400x; 1.4010x over previous
#include <cuda_runtime.h>
#include <cuda_fp16.h>
#include <mma.h>
#include <cstdint>

using namespace nvcuda;

#define NN 50000
#define NNP 50048              // 391 * 128, padded rows (zero-filled in g_xh)
#define NE 800000
#define FD 256
#define NB 196                 // (NN + 255) / 256 scan blocks

// ---------------- device scratch (no allocations allowed) ----------------
__device__ float  g_dis[NN];
__device__ int    g_cnt[NN];
__device__ int    g_off[NN];
__device__ int    g_cur[NN];
__device__ int    g_col[NE];
__device__ float  g_w[NE];
__device__ __half g_xh[(size_t)NNP * FD];  // x in fp16 (RN), padded rows = 0
__device__ __half g_wh[FD * FD];           // W in fp16 (RN)
__device__ __half g_yh[(size_t)NNP * FD];  // y = x @ W^T in fp16
__device__ int    g_blk[NB];
__device__ int    g_blkoff[NB];
__device__ int    g_is64;

__device__ __forceinline__ int edge_at(const void* ei, long long idx) {
    if (g_is64) return (int)((const long long*)ei)[idx];
    return ((const int*)ei)[idx];
}

// ---------------- cp.async helpers ----------------
__device__ __forceinline__ uint32_t smem_u32(const void* p) {
    uint32_t a;
    asm("{ .reg .u64 t; cvta.to.shared.u64 t, %1; cvt.u32.u64 %0, t; }" : "=r"(a) : "l"(p));
    return a;
}
__device__ __forceinline__ void cp_async16(uint32_t dst, const void* src) {
    asm volatile("cp.async.cg.shared.global [%0], [%1], 16;"
                 :: "r"(dst), "l"(src) : "memory");
}
#define CP_COMMIT() asm volatile("cp.async.commit_group;" ::: "memory")
#define CP_WAIT1()  asm volatile("cp.async.wait_group 1;" ::: "memory")
#define CP_WAIT0()  asm volatile("cp.async.wait_group 0;" ::: "memory")

// ---------------- fp32 -> fp16 RN conversions ----------------
// x: NNP*FD elements, 8 per thread; rows >= NN zero-filled.
__global__ __launch_bounds__(256) void k_xhalf(const float* __restrict__ x) {
    long long idx = (long long)blockIdx.x * blockDim.x + threadIdx.x;
    const long long total = (long long)NNP * FD / 8;
    if (idx >= total) return;
    size_t base = (size_t)idx * 8;
    int row = (int)(base >> 8);              // /FD
    __align__(16) __half2 h[4];
    if (row < NN) {
        float4 a = *(const float4*)(x + base);
        float4 b = *(const float4*)(x + base + 4);
        h[0] = __floats2half2_rn(a.x, a.y);
        h[1] = __floats2half2_rn(a.z, a.w);
        h[2] = __floats2half2_rn(b.x, b.y);
        h[3] = __floats2half2_rn(b.z, b.w);
    } else {
        h[0] = h[1] = h[2] = h[3] = __floats2half2_rn(0.f, 0.f);
    }
    *(uint4*)(g_xh + base) = *(const uint4*)h;
}

__global__ __launch_bounds__(256) void k_whalf(const float* __restrict__ W) {
    int idx = blockIdx.x * blockDim.x + threadIdx.x;   // FD*FD/8 = 8192 threads
    size_t base = (size_t)idx * 8;
    float4 a = *(const float4*)(W + base);
    float4 b = *(const float4*)(W + base + 4);
    __align__(16) __half2 h[4];
    h[0] = __floats2half2_rn(a.x, a.y);
    h[1] = __floats2half2_rn(a.z, a.w);
    h[2] = __floats2half2_rn(b.x, b.y);
    h[3] = __floats2half2_rn(b.z, b.w);
    *(uint4*)(g_wh + base) = *(const uint4*)h;
}

// ---------------- init + dtype detect ----------------
__global__ void k_init(const int* __restrict__ ei32) {
    int i = blockIdx.x * blockDim.x + threadIdx.x;
    if (i < NN) { g_dis[i] = 0.0f; g_cnt[i] = 0; }
    if (blockIdx.x == 0) {
        int nz = 0;
        if (threadIdx.x < 128) nz = (ei32[2 * threadIdx.x + 1] != 0) ? 1 : 0;
        int any = __syncthreads_or(nz);
        if (threadIdx.x == 0) g_is64 = (any == 0) ? 1 : 0;
    }
}

__global__ void k_deg(const void* __restrict__ ei, const float* __restrict__ C) {
    int e = blockIdx.x * blockDim.x + threadIdx.x;
    if (e < NE) {
        int r = edge_at(ei, e);
        atomicAdd(&g_dis[r], C[e]);
        atomicAdd(&g_cnt[r], 1);
    }
}

__global__ __launch_bounds__(256) void k_scan1() {
    __shared__ int s[256];
    int t = threadIdx.x;
    int i = blockIdx.x * 256 + t;
    int v = 0;
    if (i < NN) {
        float d = g_dis[i];
        g_dis[i] = (d > 0.0f) ? rsqrtf(d) : 0.0f;
        v = g_cnt[i];
    }
    s[t] = v;
    __syncthreads();
#pragma unroll
    for (int off = 128; off > 0; off >>= 1) {
        if (t < off) s[t] += s[t + off];
        __syncthreads();
    }
    if (t == 0) g_blk[blockIdx.x] = s[0];
}

__global__ __launch_bounds__(256) void k_scan2() {
    __shared__ int s[256];
    int t = threadIdx.x;
    int v = (t < NB) ? g_blk[t] : 0;
    s[t] = v;
    __syncthreads();
#pragma unroll
    for (int off = 1; off < 256; off <<= 1) {
        int u = (t >= off) ? s[t - off] : 0;
        __syncthreads();
        s[t] += u;
        __syncthreads();
    }
    if (t < NB) g_blkoff[t] = s[t] - v;
}

__global__ __launch_bounds__(256) void k_scan3() {
    __shared__ int s[256];
    int t = threadIdx.x;
    int i = blockIdx.x * 256 + t;
    int v = (i < NN) ? g_cnt[i] : 0;
    s[t] = v;
    __syncthreads();
#pragma unroll
    for (int off = 1; off < 256; off <<= 1) {
        int u = (t >= off) ? s[t - off] : 0;
        __syncthreads();
        s[t] += u;
        __syncthreads();
    }
    if (i < NN) {
        int excl = g_blkoff[blockIdx.x] + s[t] - v;
        g_off[i] = excl;
        g_cur[i] = excl;
    }
}

__global__ void k_scatter(const void* __restrict__ ei, const float* __restrict__ C) {
    int e = blockIdx.x * blockDim.x + threadIdx.x;
    if (e < NE) {
        int r  = edge_at(ei, e);
        int cl = edge_at(ei, (long long)NE + e);
        float w = g_dis[r] * C[e] * g_dis[cl];
        int p = atomicAdd(&g_cur[r], 1);
        g_col[p] = cl;
        g_w[p]   = w;
    }
}

// ---------------- fp16 tensor-core GEMM (one 128-col feature half) ------
// y_h16[:, n0:n0+128] = (half) g_xh[M,256] @ g_wh[n0:n0+128, :]^T
// Block 128x128, 8 warps (2x4), warp 64x32 (4x2 m16n16k16 fp16, fp32 acc).
// cp.async double-buffered BK=32; fp16 epilogue via smem staging.
#define GM_BM 128
#define GM_BK 32
#define BKPH  40   // padded row (halves); 80B rows

__global__ __launch_bounds__(256) void k_gemm_h(int n0) {
    __shared__ __align__(16) __half As[2][GM_BM][BKPH];   // 20 KB
    __shared__ __align__(16) __half Bs[2][GM_BM][BKPH];   // 20 KB

    const int tid  = threadIdx.x;
    const int wid  = tid >> 5;
    const int lane = tid & 31;
    const int wm = wid >> 2;     // 0..1 -> 64-row slab
    const int wn = wid & 3;      // 0..3 -> 32-col slab
    const int bm = blockIdx.x;

    wmma::fragment<wmma::accumulator, 16, 16, 16, float> acc[4][2];
#pragma unroll
    for (int i = 0; i < 4; i++)
#pragma unroll
        for (int j = 0; j < 2; j++) wmma::fill_fragment(acc[i][j], 0.0f);

    // per chunk: 128x32 halves = 512 x (8-half vec) per tile -> 2/thread/tile
    int aR[2], aC[2];
#pragma unroll
    for (int i = 0; i < 2; i++) {
        int f = tid + 256 * i;
        aR[i] = f >> 2;          // 0..127 row
        aC[i] = (f & 3) * 8;     // 0,8,16,24 halves
    }
    const __half* Asrc[2];
    const __half* Bsrc[2];
#pragma unroll
    for (int i = 0; i < 2; i++) {
        Asrc[i] = g_xh + (size_t)(bm * GM_BM + aR[i]) * FD + aC[i];   // padded, no guard
        Bsrc[i] = g_wh + (size_t)(n0 + aR[i]) * FD + aC[i];
    }

    uint32_t sa[2][2], sb[2][2];
#pragma unroll
    for (int b = 0; b < 2; b++)
#pragma unroll
        for (int i = 0; i < 2; i++) {
            sa[b][i] = smem_u32(&As[b][aR[i]][aC[i]]);
            sb[b][i] = smem_u32(&Bs[b][aR[i]][aC[i]]);
        }

    auto issue = [&](int k, int buf) {
        const int k0 = k * GM_BK;
#pragma unroll
        for (int i = 0; i < 2; i++) {
            cp_async16(sa[buf][i], Asrc[i] + k0);
            cp_async16(sb[buf][i], Bsrc[i] + k0);
        }
        CP_COMMIT();
    };

    issue(0, 0);
    issue(1, 1);
    CP_WAIT1();
    __syncthreads();

    const int NCH = FD / GM_BK; // 8
    for (int c = 0; c < NCH; c++) {
        const int p = c & 1;

#pragma unroll
        for (int ks = 0; ks < 2; ks++) {
            const int k0 = ks * 16;
            wmma::fragment<wmma::matrix_a, 16, 16, 16, __half, wmma::row_major> af[4];
            wmma::fragment<wmma::matrix_b, 16, 16, 16, __half, wmma::col_major> bf[2];
#pragma unroll
            for (int i = 0; i < 4; i++)
                wmma::load_matrix_sync(af[i], &As[p][wm * 64 + i * 16][k0], BKPH);
#pragma unroll
            for (int j = 0; j < 2; j++)
                wmma::load_matrix_sync(bf[j], &Bs[p][wn * 32 + j * 16][k0], BKPH);
#pragma unroll
            for (int i = 0; i < 4; i++)
#pragma unroll
                for (int j = 0; j < 2; j++)
                    wmma::mma_sync(acc[i][j], af[i], bf[j], acc[i][j]);
        }

        if (c < NCH - 2) {
            __syncthreads();            // all warps done with buf p
            issue(c + 2, p);
            CP_WAIT1();                 // chunk c+1 resident
            __syncthreads();
        } else if (c == NCH - 2) {
            CP_WAIT0();                 // last chunk resident
            __syncthreads();
        }
    }

    // ---------------- fp16 epilogue via smem staging ----------------
    __syncthreads();                    // retire As/Bs, reuse as staging
    float* stage = (float*)&As[0][0][0] + wid * 336;   // 16x20-float tile/warp
    const int srow = lane >> 1;
    const int scol = (lane & 1) * 8;
#pragma unroll
    for (int i = 0; i < 4; i++) {
#pragma unroll
        for (int j = 0; j < 2; j++) {
            wmma::store_matrix_sync(stage, acc[i][j], 20, wmma::mem_row_major);
            __syncwarp();
            const float* sp = stage + srow * 20 + scol;
            __align__(16) __half2 h[4];
            h[0] = __floats2half2_rn(sp[0], sp[1]);
            h[1] = __floats2half2_rn(sp[2], sp[3]);
            h[2] = __floats2half2_rn(sp[4], sp[5]);
            h[3] = __floats2half2_rn(sp[6], sp[7]);
            int gr = bm * GM_BM + wm * 64 + i * 16 + srow;
            int gc = n0 + wn * 32 + j * 16 + scol;
            *(uint4*)(g_yh + (size_t)gr * FD + gc) = *(const uint4*)h;
            __syncwarp();
        }
    }
}

// ---------------- SpMM (one 128-col feature half): warp per row ----------
__global__ __launch_bounds__(256) void k_spmm(const float* __restrict__ bias,
                                              float* __restrict__ out,
                                              int n0) {
    int gwarp = (blockIdx.x * blockDim.x + threadIdx.x) >> 5;
    int lane  = threadIdx.x & 31;
    if (gwarp >= NN) return;

    const int beg = g_off[gwarp];
    const int end = beg + g_cnt[gwarp];
    const int fc  = n0 + lane * 4;

    float4 acc = *(const float4*)(bias + fc);

    int p = beg;
    for (; p + 3 < end; p += 4) {
        int   c0 = g_col[p],     c1 = g_col[p + 1];
        int   c2 = g_col[p + 2], c3 = g_col[p + 3];
        float w0 = g_w[p],       w1 = g_w[p + 1];
        float w2 = g_w[p + 2],   w3 = g_w[p + 3];
        const __half2* y0 = (const __half2*)(g_yh + (size_t)c0 * FD + fc);
        const __half2* y1 = (const __half2*)(g_yh + (size_t)c1 * FD + fc);
        const __half2* y2 = (const __half2*)(g_yh + (size_t)c2 * FD + fc);
        const __half2* y3 = (const __half2*)(g_yh + (size_t)c3 * FD + fc);
        float2 u0 = __half22float2(y0[0]), u1 = __half22float2(y0[1]);
        float2 v0 = __half22float2(y1[0]), v1 = __half22float2(y1[1]);
        float2 s0 = __half22float2(y2[0]), s1 = __half22float2(y2[1]);
        float2 t0 = __half22float2(y3[0]), t1 = __half22float2(y3[1]);
        acc.x = fmaf(w0, u0.x, acc.x); acc.y = fmaf(w0, u0.y, acc.y);
        acc.z = fmaf(w0, u1.x, acc.z); acc.w = fmaf(w0, u1.y, acc.w);
        acc.x = fmaf(w1, v0.x, acc.x); acc.y = fmaf(w1, v0.y, acc.y);
        acc.z = fmaf(w1, v1.x, acc.z); acc.w = fmaf(w1, v1.y, acc.w);
        acc.x = fmaf(w2, s0.x, acc.x); acc.y = fmaf(w2, s0.y, acc.y);
        acc.z = fmaf(w2, s1.x, acc.z); acc.w = fmaf(w2, s1.y, acc.w);
        acc.x = fmaf(w3, t0.x, acc.x); acc.y = fmaf(w3, t0.y, acc.y);
        acc.z = fmaf(w3, t1.x, acc.z); acc.w = fmaf(w3, t1.y, acc.w);
    }
    for (; p < end; p++) {
        float wv = g_w[p];
        const __half2* yr = (const __half2*)(g_yh + (size_t)g_col[p] * FD + fc);
        float2 u0 = __half22float2(yr[0]), u1 = __half22float2(yr[1]);
        acc.x = fmaf(wv, u0.x, acc.x); acc.y = fmaf(wv, u0.y, acc.y);
        acc.z = fmaf(wv, u1.x, acc.z); acc.w = fmaf(wv, u1.y, acc.w);
    }

    *(float4*)(out + (size_t)gwarp * FD + fc) = acc;
}

// ---------------- launch: cvt -> two-half GEMM/SpMM pipeline -------------
extern "C" void kernel_launch(void* const* d_in, const int* in_sizes, int n_in,
                              void* d_out, int out_size) {
    const float* x  = (const float*)d_in[0];
    const void*  ei = d_in[1];
    const float* C  = (const float*)d_in[2];
    const float* W  = (const float*)d_in[3];
    const float* b  = (const float*)d_in[4];
    float* out = (float*)d_out;

    cudaStream_t s2;
    cudaStreamCreateWithFlags(&s2, cudaStreamNonBlocking);
    cudaEvent_t eFork, e0, e1;
    cudaEventCreateWithFlags(&eFork, cudaEventDisableTiming);
    cudaEventCreateWithFlags(&e0, cudaEventDisableTiming);
    cudaEventCreateWithFlags(&e1, cudaEventDisableTiming);

    const int xBlocks = (int)(((long long)NNP * FD / 8 + 255) / 256);

    cudaEventRecord(eFork, 0);
    cudaStreamWaitEvent(s2, eFork, 0);
    k_xhalf<<<xBlocks, 256, 0, s2>>>(x);
    k_whalf<<<FD * FD / 8 / 256, 256, 0, s2>>>(W);
    k_gemm_h<<<NNP / GM_BM, 256, 0, s2>>>(0);
    cudaEventRecord(e0, s2);
    k_gemm_h<<<NNP / GM_BM, 256, 0, s2>>>(128);
    cudaEventRecord(e1, s2);

    // CSR build pipeline on the default stream (hidden under cvt+GEMM_h0)
    k_init<<<(NN + 255) / 256, 256>>>((const int*)ei);
    k_deg<<<(NE + 255) / 256, 256>>>(ei, C);
    k_scan1<<<NB, 256>>>();
    k_scan2<<<1, 256>>>();
    k_scan3<<<NB, 256>>>();
    k_scatter<<<(NE + 255) / 256, 256>>>(ei, C);

    // SpMM_h0 overlaps GEMM_h1; SpMM_h1 after GEMM_h1
    cudaStreamWaitEvent(0, e0, 0);
    k_spmm<<<(NN * 32 + 255) / 256, 256>>>(b, out, 0);
    cudaStreamWaitEvent(0, e1, 0);
    k_spmm<<<(NN * 32 + 255) / 256, 256>>>(b, out, 128);
}